// round 16
// baseline (speedup 1.0000x reference)
#include <cuda_runtime.h>
#include <cuda_bf16.h>
#include <math.h>
#include <stdint.h>

// Problem constants
#define BN     16384           // B*N tokens
#define DIM    512
#define NC     4096            // codes per stage
#define NQ     4               // stages
#define CBSZ   (NC * DIM)      // floats per stage codebook
#define QOUT_ELEMS  (BN * DIM)               // 8388608
#define IDX_OFF     QOUT_ELEMS
#define IDX_ELEMS   (BN * NQ)                // 65536
#define LOSS_OFF    (IDX_OFF + IDX_ELEMS)
#define OUT_FULL    (LOSS_OFF + NQ)

typedef unsigned long long ull;

// ---------------- device scratch (static globals; no runtime alloc) ----------
__device__ float  g_cbn[(size_t)NQ * CBSZ];     // normalized implicit codebooks (32MB)
__device__ float  g_res[(size_t)BN * DIM];      // residual (32MB)
__device__ float  g_innorm[BN];                 // 1/||residual|| per token
__device__ __align__(16) uint32_t g_cbq[(size_t)NQ * CBSZ / 4];  // cb_n int8 (8MB)
__device__ __align__(16) uint32_t g_xq[(size_t)BN * DIM / 4];    // x_n int8 (8MB)
__device__ float  g_cbsc[NQ * NC];              // per-code dequant scale
__device__ float  g_xsc[BN];                    // per-token dequant scale
__device__ ull    g_best[BN];                   // packed (keyed exact sim, ~idx)
__device__ double g_loss[NQ];

// ---------------- helpers ------------------------------------------------------
__device__ __forceinline__ uint32_t smem_to_u32(const void* p) {
    uint32_t a;
    asm("{ .reg .u64 t; cvta.to.shared.u64 t, %1; cvt.u32.u64 %0, t; }" : "=r"(a) : "l"(p));
    return a;
}
__device__ __forceinline__ float warp_sum(float v) {
    #pragma unroll
    for (int o = 16; o; o >>= 1) v += __shfl_xor_sync(0xffffffffu, v, o);
    return v;
}
__device__ __forceinline__ float warp_max(float v) {
    #pragma unroll
    for (int o = 16; o; o >>= 1) v = fmaxf(v, __shfl_xor_sync(0xffffffffu, v, o));
    return v;
}

// order-preserving float<->uint key
__device__ __forceinline__ uint32_t kf(float v) {
    unsigned u = __float_as_uint(v);
    return (u & 0x80000000u) ? ~u : (u | 0x80000000u);
}
__device__ __forceinline__ float unkf(uint32_t k) {
    return (k & 0x80000000u) ? __uint_as_float(k ^ 0x80000000u)
                             : __uint_as_float(~k);
}
// packed (key, ~idx): atomicMax picks max value, then smallest index.
__device__ __forceinline__ ull pack_key(float v, int idx) {
    return ((ull)kf(v) << 32) | (ull)(0xFFFFFFFFu - (unsigned)idx);
}

// ldmatrix / mma (baseline PTX ISA — valid for plain sm_103 target)
__device__ __forceinline__ void ldm_x4(uint32_t* r, uint32_t addr) {
    asm volatile("ldmatrix.sync.aligned.m8n8.x4.shared.b16 {%0,%1,%2,%3}, [%4];"
        : "=r"(r[0]), "=r"(r[1]), "=r"(r[2]), "=r"(r[3]) : "r"(addr));
}
__device__ __forceinline__ void mma_bf16(float* d, const uint32_t* a, const uint32_t* b) {
    asm volatile(
        "mma.sync.aligned.m16n8k16.row.col.f32.bf16.bf16.f32 "
        "{%0,%1,%2,%3}, {%4,%5,%6,%7}, {%8,%9}, {%0,%1,%2,%3};"
        : "+f"(d[0]), "+f"(d[1]), "+f"(d[2]), "+f"(d[3])
        : "r"(a[0]), "r"(a[1]), "r"(a[2]), "r"(a[3]), "r"(b[0]), "r"(b[1]));
}
// int8 mma: same fragment byte-layout as bf16-k16, 2x K per instruction
__device__ __forceinline__ void mma_s8(int* d, const uint32_t* a, const uint32_t* b) {
    asm volatile(
        "mma.sync.aligned.m16n8k32.row.col.s32.s8.s8.s32 "
        "{%0,%1,%2,%3}, {%4,%5,%6,%7}, {%8,%9}, {%0,%1,%2,%3};"
        : "+r"(d[0]), "+r"(d[1]), "+r"(d[2]), "+r"(d[3])
        : "r"(a[0]), "r"(a[1]), "r"(a[2]), "r"(a[3]), "r"(b[0]), "r"(b[1]));
}
__device__ __forceinline__ void cp16(uint32_t saddr, const void* gptr) {
    asm volatile("cp.async.cg.shared.global [%0], [%1], 16;"
        :: "r"(saddr), "l"(gptr) : "memory");
}
#define CP_COMMIT() asm volatile("cp.async.commit_group;" ::: "memory")
#define CP_WAIT0()  asm volatile("cp.async.wait_group 0;" ::: "memory")

#define SWZ(off) ((off) ^ (((off) >> 3) & 0x70u))

// bf16 split packing (cb_gemm only)
__device__ __forceinline__ uint32_t pack_bf16(float e0, float e1) {
    uint32_t r; asm("cvt.rn.bf16x2.f32 %0, %1, %2;" : "=r"(r) : "f"(e1), "f"(e0)); return r;
}
__device__ __forceinline__ float bflo(uint32_t p) { return __uint_as_float(p << 16); }
__device__ __forceinline__ float bfhi(uint32_t p) { return __uint_as_float(p & 0xffff0000u); }

__device__ __forceinline__ void cvt_store8(char* hb, char* lb, uint32_t sw,
                                           float4 a, float4 b) {
    uint4 hv, lv;
    hv.x = pack_bf16(a.x, a.y); hv.y = pack_bf16(a.z, a.w);
    hv.z = pack_bf16(b.x, b.y); hv.w = pack_bf16(b.z, b.w);
    lv.x = pack_bf16(a.x - bflo(hv.x), a.y - bfhi(hv.x));
    lv.y = pack_bf16(a.z - bflo(hv.y), a.w - bfhi(hv.y));
    lv.z = pack_bf16(b.x - bflo(hv.z), b.y - bfhi(hv.z));
    lv.w = pack_bf16(b.z - bflo(hv.w), b.w - bfhi(hv.w));
    *(uint4*)(hb + sw) = hv;
    *(uint4*)(lb + sw) = lv;
}

// quantize 4 floats to packed s8 (invs = 127/maxabs)
__device__ __forceinline__ uint32_t pack_s8(float4 v, float invs) {
    int q0 = __float2int_rn(v.x * invs);
    int q1 = __float2int_rn(v.y * invs);
    int q2 = __float2int_rn(v.z * invs);
    int q3 = __float2int_rn(v.w * invs);
    return (uint32_t)(q0 & 0xFF) | ((uint32_t)(q1 & 0xFF) << 8)
         | ((uint32_t)(q2 & 0xFF) << 16) | ((uint32_t)(q3 & 0xFF) << 24);
}
__device__ __forceinline__ float max4(float4 v) {
    return fmaxf(fmaxf(fabsf(v.x), fabsf(v.y)), fmaxf(fabsf(v.z), fabsf(v.w)));
}

// ---------------- misc small kernels -----------------------------------------
__global__ void zero_state_kernel() {
    g_best[blockIdx.x * 1024 + threadIdx.x] = 0ull;
    if (blockIdx.x == 0 && threadIdx.x < NQ) g_loss[threadIdx.x] = 0.0;
}
__global__ void finalize_loss_kernel(float* out) {
    if (threadIdx.x < NQ)
        out[LOSS_OFF + threadIdx.x] =
            (float)(g_loss[threadIdx.x] * 1.25 / (double)QOUT_ELEMS);
}

// residual = x ; inv = 1/max(||x||,1e-12) ; int8 quant of x*inv
__global__ void init_xr_kernel(const float* __restrict__ x) {
    int row = blockIdx.x;
    int t   = threadIdx.x;
    const float4* xr = (const float4*)(x + (size_t)row * DIM);
    float4 v = xr[t];
    float s = v.x * v.x + v.y * v.y + v.z * v.z + v.w * v.w;
    s = warp_sum(s);
    __shared__ float ps[4], pm[4];
    if ((t & 31) == 0) ps[t >> 5] = s;
    __syncthreads();
    float tot = ps[0] + ps[1] + ps[2] + ps[3];
    float inv = 1.0f / fmaxf(sqrtf(tot), 1e-12f);
    ((float4*)(g_res + (size_t)row * DIM))[t] = v;
    if (t == 0) g_innorm[row] = inv;
    float4 n = make_float4(v.x * inv, v.y * inv, v.z * inv, v.w * inv);
    float m = warp_max(max4(n));
    if ((t & 31) == 0) pm[t >> 5] = m;
    __syncthreads();
    float ma = fmaxf(fmaxf(pm[0], pm[1]), fmaxf(pm[2], pm[3]));
    float invs = 127.f / fmaxf(ma, 1e-20f);
    g_xq[(size_t)row * (DIM / 4) + t] = pack_s8(n, invs);
    if (t == 0) g_xsc[row] = ma * (1.f / 127.f);
}

// in-place row l2norm of g_cbn + int8 quant (one block per row)
__global__ void cb_norm_kernel() {
    size_t row = blockIdx.x;
    int t = threadIdx.x;
    float4* r = (float4*)(g_cbn + row * DIM);
    float4 v = r[t];
    float s = v.x * v.x + v.y * v.y + v.z * v.z + v.w * v.w;
    s = warp_sum(s);
    __shared__ float ps[4], pm[4];
    if ((t & 31) == 0) ps[t >> 5] = s;
    __syncthreads();
    float tot = ps[0] + ps[1] + ps[2] + ps[3];
    float inv = 1.0f / fmaxf(sqrtf(tot), 1e-12f);
    float4 n = make_float4(v.x * inv, v.y * inv, v.z * inv, v.w * inv);
    r[t] = n;
    float m = warp_max(max4(n));
    if ((t & 31) == 0) pm[t >> 5] = m;
    __syncthreads();
    float ma = fmaxf(fmaxf(pm[0], pm[1]), fmaxf(pm[2], pm[3]));
    float invs = 127.f / fmaxf(ma, 1e-20f);
    g_cbq[row * (DIM / 4) + t] = pack_s8(n, invs);
    if (t == 0) g_cbsc[row] = ma * (1.f / 127.f);
}

// ============ implicit codebook GEMM via bf16 split-2 mma ======================
#define XH_O 0
#define XL_O 16384
#define CH_O 32768
#define CL_O 49152
#define CB_SMEM 131072            // 2 x 64KB buffers

__global__ void __launch_bounds__(256, 1)
cb_gemm_mma_kernel(const float* __restrict__ codebooks, const float* __restrict__ weights) {
    extern __shared__ __align__(16) char smem[];
    uint32_t sb = smem_to_u32(smem);

    int tid  = threadIdx.x;
    int lane = tid & 31;
    int warp = tid >> 5;
    int wm = warp & 3;
    int wn = warp >> 2;

    int stage = blockIdx.z;
    int m0 = blockIdx.x * 128;    // codes
    int n0 = blockIdx.y * 128;    // dims
    const float* A  = codebooks + (size_t)stage * NC * DIM;
    const float* Bw = weights   + (size_t)stage * DIM * DIM;

    int srow[4], sslot[4];
    uint32_t ssw[4];
    #pragma unroll
    for (int it = 0; it < 4; it++) {
        int item = it * 256 + tid;
        srow[it]  = item >> 3;
        sslot[it] = item & 7;
        uint32_t off = (uint32_t)srow[it] * 128u + (uint32_t)sslot[it] * 16u;
        ssw[it] = SWZ(off);
    }

    int a_r = wm * 32 + (lane & 15);
    int a_c = (lane >> 4) << 4;
    int b_r = wn * 64 + ((lane >> 4) << 3) + (lane & 7);
    int b_c = ((lane >> 3) & 1) << 4;

    float acc[2][8][4];
    #pragma unroll
    for (int mf = 0; mf < 2; mf++)
        #pragma unroll
        for (int nf = 0; nf < 8; nf++)
            #pragma unroll
            for (int q = 0; q < 4; q++) acc[mf][nf][q] = 0.f;

    float4 xv[4][2], cv[4][2];
    #pragma unroll
    for (int it = 0; it < 4; it++) {
        const float* xp = A  + (size_t)(m0 + srow[it]) * DIM + sslot[it] * 8;
        const float* cp = Bw + (size_t)(n0 + srow[it]) * DIM + sslot[it] * 8;
        xv[it][0] = *(const float4*)xp;  xv[it][1] = *(const float4*)(xp + 4);
        cv[it][0] = *(const float4*)cp;  cv[it][1] = *(const float4*)(cp + 4);
    }
    #pragma unroll
    for (int it = 0; it < 4; it++) {
        cvt_store8(smem + XH_O, smem + XL_O, ssw[it], xv[it][0], xv[it][1]);
        cvt_store8(smem + CH_O, smem + CL_O, ssw[it], cv[it][0], cv[it][1]);
    }
    __syncthreads();

    for (int g = 0; g < 8; g++) {
        if (g + 1 < 8) {
            int k1 = (g + 1) * 64;
            #pragma unroll
            for (int it = 0; it < 4; it++) {
                const float* xp = A  + (size_t)(m0 + srow[it]) * DIM + k1 + sslot[it] * 8;
                const float* cp = Bw + (size_t)(n0 + srow[it]) * DIM + k1 + sslot[it] * 8;
                xv[it][0] = *(const float4*)xp;  xv[it][1] = *(const float4*)(xp + 4);
                cv[it][0] = *(const float4*)cp;  cv[it][1] = *(const float4*)(cp + 4);
            }
        }
        uint32_t bufb = sb + (uint32_t)((g & 1) * 65536);
        #pragma unroll
        for (int ks = 0; ks < 4; ks++) {
            uint32_t ah[2][4], al[2][4];
            #pragma unroll
            for (int mf = 0; mf < 2; mf++) {
                uint32_t off = (uint32_t)(a_r + mf * 16) * 128u + (uint32_t)(ks * 32 + a_c);
                uint32_t sw = SWZ(off);
                ldm_x4(ah[mf], bufb + XH_O + sw);
                ldm_x4(al[mf], bufb + XL_O + sw);
            }
            uint32_t bh[16], bl[16];
            #pragma unroll
            for (int nf2 = 0; nf2 < 4; nf2++) {
                uint32_t off = (uint32_t)(b_r + nf2 * 16) * 128u + (uint32_t)(ks * 32 + b_c);
                uint32_t sw = SWZ(off);
                ldm_x4(&bh[nf2 * 4], bufb + CH_O + sw);
                ldm_x4(&bl[nf2 * 4], bufb + CL_O + sw);
            }
            #pragma unroll
            for (int mf = 0; mf < 2; mf++)
                #pragma unroll
                for (int nf = 0; nf < 8; nf++) {
                    mma_bf16(acc[mf][nf], ah[mf], &bh[nf * 2]);
                    mma_bf16(acc[mf][nf], ah[mf], &bl[nf * 2]);
                    mma_bf16(acc[mf][nf], al[mf], &bh[nf * 2]);
                }
        }
        if (g + 1 < 8) {
            char* nb = smem + ((g + 1) & 1) * 65536;
            #pragma unroll
            for (int it = 0; it < 4; it++) {
                cvt_store8(nb + XH_O, nb + XL_O, ssw[it], xv[it][0], xv[it][1]);
                cvt_store8(nb + CH_O, nb + CL_O, ssw[it], cv[it][0], cv[it][1]);
            }
        }
        __syncthreads();
    }

    float* out = g_cbn + (size_t)stage * CBSZ;
    int r0 = lane >> 2, c0 = (lane & 3) * 2;
    #pragma unroll
    for (int mf = 0; mf < 2; mf++) {
        int row = m0 + wm * 32 + mf * 16 + r0;
        #pragma unroll
        for (int nf = 0; nf < 8; nf++) {
            int col = n0 + wn * 64 + nf * 8 + c0;
            out[(size_t)row * DIM + col]           = acc[mf][nf][0];
            out[(size_t)row * DIM + col + 1]       = acc[mf][nf][1];
            out[(size_t)(row + 8) * DIM + col]     = acc[mf][nf][2];
            out[(size_t)(row + 8) * DIM + col + 1] = acc[mf][nf][3];
        }
    }
}

// ============ fused sim: int8 coarse (exact s32) + candidate lists + rescore ===
// CTA = (token-tile of 128) x (code-sixteenth of 256) -> 2048 CTAs, occ 2.
// K-chunk = 128 int8 = 128B rows (same SW128 path as bf16, 2x K per mma).
// Tile boundary: dequant (exact: s32 < 2^24) -> per-row best -> candidate list.
// End: exact fp32 dots for candidates, packed-atomicMax merge.
#define FXQ_O   0
#define FCQ_O   16384
#define FBUFSZ  32768
#define XSC_O   65536                       // 128 floats
#define CSC_O   (XSC_O + 512)               // 256 floats
#define BEST_O  (CSC_O + 1024)              // 128 x u32
#define CNT_O   (BEST_O + 512)              // 128 x int
#define OVF_O   (CNT_O + 512)               // 128 x int
#define CAND_O  (OVF_O + 512)               // 128 x 16 x u64
#define CAND_CAP 16
#define FUSED_SMEM (CAND_O + 128 * CAND_CAP * 8)   // 84992 B
#define FGTOT 8                             // 2 n-tiles x 4 k-chunks (K=128 each)
#define RESCORE_MARGIN 0.009f

__global__ void __launch_bounds__(256, 2)
sim_fused_kernel(int stage) {
    extern __shared__ __align__(16) char smem[];
    uint32_t sb = smem_to_u32(smem);

    int tid  = threadIdx.x;
    int lane = tid & 31;
    int warp = tid >> 5;
    int wm = warp & 1;            // m offset wm*64
    int wn = warp >> 1;           // n offset wn*32

    int tilei = blockIdx.x >> 4;
    int six   = blockIdx.x & 15;
    int m0 = tilei * 128;
    int eb = six * 256;

    const char* xqp = (const char*)g_xq + (size_t)m0 * DIM;
    const char* cqp = (const char*)g_cbq + (size_t)stage * CBSZ + (size_t)eb * DIM;

    float*    xsc  = (float*)(smem + XSC_O);
    float*    csc  = (float*)(smem + CSC_O);
    uint32_t* best = (uint32_t*)(smem + BEST_O);
    int*      cnt  = (int*)(smem + CNT_O);
    int*      ovf  = (int*)(smem + OVF_O);
    ull*      cand = (ull*)(smem + CAND_O);

    if (tid < 128) {
        best[tid] = 0u; cnt[tid] = 0; ovf[tid] = 0;
        xsc[tid] = g_xsc[m0 + tid];
    }
    csc[tid] = g_cbsc[stage * NC + eb + tid];

    int srow[4], sslot[4];
    uint32_t ssw[4];
    size_t roff[4];
    #pragma unroll
    for (int it = 0; it < 4; it++) {
        int item = it * 256 + tid;
        srow[it]  = item >> 3;
        sslot[it] = item & 7;
        uint32_t off = (uint32_t)srow[it] * 128u + (uint32_t)sslot[it] * 16u;
        ssw[it] = SWZ(off);
        roff[it] = (size_t)srow[it] * DIM + (size_t)sslot[it] * 16;
    }

    int a_r = wm * 64 + (lane & 15);
    int a_c = (lane >> 4) << 4;
    int b_r = wn * 32 + ((lane >> 4) << 3) + (lane & 7);
    int b_c = ((lane >> 3) & 1) << 4;

    int acc[4][4][4];
    #pragma unroll
    for (int mf = 0; mf < 4; mf++)
        #pragma unroll
        for (int nf = 0; nf < 4; nf++)
            #pragma unroll
            for (int q = 0; q < 4; q++) acc[mf][nf][q] = 0;

    // prologue: async-copy chunk 0 into buf 0
    {
        uint32_t nb = sb;
        #pragma unroll
        for (int it = 0; it < 4; it++) {
            cp16(nb + FXQ_O + ssw[it], xqp + roff[it]);
            cp16(nb + FCQ_O + ssw[it], cqp + roff[it]);
        }
        CP_COMMIT();
        CP_WAIT0();
        __syncthreads();
    }

    for (int gg = 0; gg < FGTOT; gg++) {
        if (gg + 1 < FGTOT) {
            int nt1 = (gg + 1) >> 2;
            size_t kb1 = (size_t)(((gg + 1) & 3) * 128);
            size_t cb1 = (size_t)(nt1 * 128) * DIM + kb1;
            uint32_t nb = sb + (uint32_t)(((gg + 1) & 1) * FBUFSZ);
            #pragma unroll
            for (int it = 0; it < 4; it++) {
                cp16(nb + FXQ_O + ssw[it], xqp + kb1 + roff[it]);
                cp16(nb + FCQ_O + ssw[it], cqp + cb1 + roff[it]);
            }
            CP_COMMIT();
        }
        uint32_t bufb = sb + (uint32_t)((gg & 1) * FBUFSZ);
        #pragma unroll
        for (int ks = 0; ks < 4; ks++) {
            uint32_t ah[4][4];
            #pragma unroll
            for (int mf = 0; mf < 4; mf++) {
                uint32_t off = (uint32_t)(a_r + mf * 16) * 128u + (uint32_t)(ks * 32 + a_c);
                ldm_x4(ah[mf], bufb + FXQ_O + SWZ(off));
            }
            uint32_t bh[8];
            #pragma unroll
            for (int nf2 = 0; nf2 < 2; nf2++) {
                uint32_t off = (uint32_t)(b_r + nf2 * 16) * 128u + (uint32_t)(ks * 32 + b_c);
                ldm_x4(&bh[nf2 * 4], bufb + FCQ_O + SWZ(off));
            }
            #pragma unroll
            for (int mf = 0; mf < 4; mf++)
                #pragma unroll
                for (int nf = 0; nf < 4; nf++)
                    mma_s8(acc[mf][nf], ah[mf], &bh[nf * 2]);
        }
        // n-tile boundary: dequant, per-row best, then candidate append
        if ((gg & 3) == 3) {
            int nt = gg >> 2;
            // phase A: per-row max of this thread's dequantized values
            #pragma unroll
            for (int mf = 0; mf < 4; mf++) {
                int r0 = wm * 64 + mf * 16 + (lane >> 2);
                float sxa = xsc[r0], sxb = xsc[r0 + 8];
                float v0m = -1e30f, v1m = -1e30f;
                #pragma unroll
                for (int nf = 0; nf < 4; nf++) {
                    int cl = nt * 128 + wn * 32 + (lane & 3) * 2 + nf * 8;
                    float sc0 = csc[cl], sc1 = csc[cl + 1];
                    v0m = fmaxf(v0m, fmaxf((float)acc[mf][nf][0] * sxa * sc0,
                                           (float)acc[mf][nf][1] * sxa * sc1));
                    v1m = fmaxf(v1m, fmaxf((float)acc[mf][nf][2] * sxb * sc0,
                                           (float)acc[mf][nf][3] * sxb * sc1));
                }
                atomicMax(&best[r0], kf(v0m));
                atomicMax(&best[r0 + 8], kf(v1m));
            }
            __syncthreads();
            // phase B: append candidates within margin of (current) best
            #pragma unroll
            for (int mf = 0; mf < 4; mf++) {
                int r0 = wm * 64 + mf * 16 + (lane >> 2);
                int r1 = r0 + 8;
                float sxa = xsc[r0], sxb = xsc[r1];
                float t0 = unkf(best[r0]) - RESCORE_MARGIN;
                float t1 = unkf(best[r1]) - RESCORE_MARGIN;
                #pragma unroll
                for (int nf = 0; nf < 4; nf++) {
                    int cl = nt * 128 + wn * 32 + (lane & 3) * 2 + nf * 8;
                    float sc0 = csc[cl], sc1 = csc[cl + 1];
                    int code = eb + cl;
                    float v0 = (float)acc[mf][nf][0] * sxa * sc0;
                    float v1 = (float)acc[mf][nf][1] * sxa * sc1;
                    float v2 = (float)acc[mf][nf][2] * sxb * sc0;
                    float v3 = (float)acc[mf][nf][3] * sxb * sc1;
                    if (v0 >= t0) {
                        int p = atomicAdd(&cnt[r0], 1);
                        if (p < CAND_CAP) cand[r0 * CAND_CAP + p] = ((ull)kf(v0) << 32) | (unsigned)code;
                        else ovf[r0] = 1;
                    }
                    if (v1 >= t0) {
                        int p = atomicAdd(&cnt[r0], 1);
                        if (p < CAND_CAP) cand[r0 * CAND_CAP + p] = ((ull)kf(v1) << 32) | (unsigned)(code + 1);
                        else ovf[r0] = 1;
                    }
                    if (v2 >= t1) {
                        int p = atomicAdd(&cnt[r1], 1);
                        if (p < CAND_CAP) cand[r1 * CAND_CAP + p] = ((ull)kf(v2) << 32) | (unsigned)code;
                        else ovf[r1] = 1;
                    }
                    if (v3 >= t1) {
                        int p = atomicAdd(&cnt[r1], 1);
                        if (p < CAND_CAP) cand[r1 * CAND_CAP + p] = ((ull)kf(v3) << 32) | (unsigned)(code + 1);
                        else ovf[r1] = 1;
                    }
                    acc[mf][nf][0] = 0; acc[mf][nf][1] = 0;
                    acc[mf][nf][2] = 0; acc[mf][nf][3] = 0;
                }
            }
        }
        if (gg + 1 < FGTOT) CP_WAIT0();
        __syncthreads();
    }

    // ---------- rescore: each warp owns 16 tokens ----------
    const float* cbs = g_cbn + (size_t)stage * CBSZ;
    for (int ti = 0; ti < 16; ti++) {
        int row = warp * 16 + ti;
        int token = m0 + row;

        float invx = g_innorm[token];
        const float4* xr = (const float4*)(g_res + (size_t)token * DIM);
        float4 xv[4];
        #pragma unroll
        for (int k = 0; k < 4; k++) {
            float4 v = xr[lane + k * 32];
            xv[k] = make_float4(v.x * invx, v.y * invx, v.z * invx, v.w * invx);
        }

        float thr = unkf(best[row]) - RESCORE_MARGIN;
        float bestv = -1e30f;
        int   besti = NC;

        if (!ovf[row]) {
            int n = cnt[row]; if (n > CAND_CAP) n = CAND_CAP;
            for (int i = 0; i < n; i++) {
                ull e = cand[row * CAND_CAP + i];
                float cv = unkf((uint32_t)(e >> 32));
                if (cv < thr) continue;     // stale-best over-append: skip
                int code = (int)(e & 0xFFFFFFFFull);
                const float4* cbr = (const float4*)(cbs + (size_t)code * DIM);
                float s = 0.f;
                #pragma unroll
                for (int k = 0; k < 4; k++) {
                    float4 c = cbr[lane + k * 32];
                    s += c.x * xv[k].x + c.y * xv[k].y + c.z * xv[k].z + c.w * xv[k].w;
                }
                s = warp_sum(s);
                if (s > bestv || (s == bestv && code < besti)) { bestv = s; besti = code; }
            }
        } else {
            // overflow fallback: exact dots over the whole sixteenth
            for (int c = 0; c < 256; c++) {
                int code = eb + c;
                const float4* cbr = (const float4*)(cbs + (size_t)code * DIM);
                float s = 0.f;
                #pragma unroll
                for (int k = 0; k < 4; k++) {
                    float4 cc = cbr[lane + k * 32];
                    s += cc.x * xv[k].x + cc.y * xv[k].y + cc.z * xv[k].z + cc.w * xv[k].w;
                }
                s = warp_sum(s);
                if (s > bestv || (s == bestv && code < besti)) { bestv = s; besti = code; }
            }
        }
        if (lane == 0)
            atomicMax(&g_best[token], pack_key(bestv, besti));
    }
}

// ---------------- rotation-trick update per token ------------------------------
// Also resets g_best[token] = 0 and writes next stage's int8 x_n.
__global__ void rotate_update_kernel(int stage, float* __restrict__ out, int write_aux) {
    int warp = threadIdx.x >> 5;
    int lane = threadIdx.x & 31;
    int token = blockIdx.x * 8 + warp;

    float4* rr = (float4*)(g_res + (size_t)token * DIM);
    float invx = g_innorm[token];
    ull bkey = g_best[token];
    int code = (int)(0xFFFFFFFFu - (unsigned)(bkey & 0xFFFFFFFFull));
    const float4* qr = (const float4*)(g_cbn + (size_t)stage * CBSZ + (size_t)code * DIM);

    float4 xv[4], qv[4], rv[4];
    float see = 0.f, stt = 0.f, set = 0.f;
    #pragma unroll
    for (int j = 0; j < 4; j++) {
        rv[j] = rr[lane + j * 32];
        xv[j] = make_float4(rv[j].x * invx, rv[j].y * invx,
                            rv[j].z * invx, rv[j].w * invx);
        qv[j] = qr[lane + j * 32];
        see += xv[j].x * xv[j].x + xv[j].y * xv[j].y + xv[j].z * xv[j].z + xv[j].w * xv[j].w;
        stt += qv[j].x * qv[j].x + qv[j].y * qv[j].y + qv[j].z * qv[j].z + qv[j].w * qv[j].w;
        set += xv[j].x * qv[j].x + xv[j].y * qv[j].y + xv[j].z * qv[j].z + xv[j].w * qv[j].w;
    }
    see = warp_sum(see); stt = warp_sum(stt); set = warp_sum(set);

    float ns = sqrtf(see), nt = sqrtf(stt);
    float eu = see / ns;
    float eq = set / nt;
    float nw2 = 2.f + 2.f * set / (ns * nt);
    float nw = fmaxf(sqrtf(nw2), 1e-12f);
    float cw = 2.f * (eu + eq) / (nw * nw);
    float ax = (nt / ns) * (1.f - cw / ns);
    float aq = (2.f * eu - cw) / ns;
    float scc = see - 2.f * set + stt;

    float4* qo = (float4*)(out + (size_t)token * DIM);
    float rn2 = 0.f;
    float4 rnv[4];
    #pragma unroll
    for (int j = 0; j < 4; j++) {
        float4 o;
        o.x = ax * xv[j].x + aq * qv[j].x;
        o.y = ax * xv[j].y + aq * qv[j].y;
        o.z = ax * xv[j].z + aq * qv[j].z;
        o.w = ax * xv[j].w + aq * qv[j].w;
        if (stage == 0) {
            qo[lane + j * 32] = o;
        } else {
            float4 prev = qo[lane + j * 32];
            prev.x += o.x; prev.y += o.y; prev.z += o.z; prev.w += o.w;
            qo[lane + j * 32] = prev;
        }
        float4 rn;
        rn.x = rv[j].x - o.x; rn.y = rv[j].y - o.y;
        rn.z = rv[j].z - o.z; rn.w = rv[j].w - o.w;
        rr[lane + j * 32] = rn;
        rnv[j] = rn;
        rn2 += rn.x * rn.x + rn.y * rn.y + rn.z * rn.z + rn.w * rn.w;
    }
    if (stage < NQ - 1) {
        rn2 = warp_sum(rn2);
        float inv = 1.f / fmaxf(sqrtf(rn2), 1e-12f);
        if (lane == 0) g_innorm[token] = inv;
        float4 nv[4];
        float m = 0.f;
        #pragma unroll
        for (int j = 0; j < 4; j++) {
            nv[j] = make_float4(rnv[j].x * inv, rnv[j].y * inv,
                                rnv[j].z * inv, rnv[j].w * inv);
            m = fmaxf(m, max4(nv[j]));
        }
        m = warp_max(m);
        float invs = 127.f / fmaxf(m, 1e-20f);
        uint32_t* xqw = g_xq + (size_t)token * (DIM / 4);
        #pragma unroll
        for (int j = 0; j < 4; j++)
            xqw[lane + j * 32] = pack_s8(nv[j], invs);
        if (lane == 0) g_xsc[token] = m * (1.f / 127.f);
    }
    if (lane == 0) {
        if (write_aux)
            out[IDX_OFF + (size_t)token * NQ + stage] = (float)code;
        g_best[token] = 0ull;    // reset for next stage
    }

    __shared__ float wscc[8];
    if (lane == 0) wscc[warp] = scc;
    __syncthreads();
    if (threadIdx.x == 0) {
        float s = 0.f;
        #pragma unroll
        for (int w = 0; w < 8; w++) s += wscc[w];
        atomicAdd(&g_loss[stage], (double)s);
    }
}

// ---------------- launch ------------------------------------------------------
extern "C" void kernel_launch(void* const* d_in, const int* in_sizes, int n_in,
                              void* d_out, int out_size) {
    const float* x         = (const float*)d_in[0];
    const float* codebooks = (const float*)d_in[1];
    const float* weights   = (const float*)d_in[2];
    float* out = (float*)d_out;
    int write_aux = (out_size >= OUT_FULL) ? 1 : 0;

    cudaFuncSetAttribute(cb_gemm_mma_kernel,
                         cudaFuncAttributeMaxDynamicSharedMemorySize, CB_SMEM);
    cudaFuncSetAttribute(sim_fused_kernel,
                         cudaFuncAttributeMaxDynamicSharedMemorySize, FUSED_SMEM);

    zero_state_kernel<<<BN / 1024, 1024>>>();
    cb_gemm_mma_kernel<<<dim3(NC / 128, DIM / 128, NQ), 256, CB_SMEM>>>(codebooks, weights);
    cb_norm_kernel<<<NQ * NC, 128>>>();
    init_xr_kernel<<<BN, 128>>>(x);
    for (int s = 0; s < NQ; s++) {
        sim_fused_kernel<<<(BN / 128) * 16, 256, FUSED_SMEM>>>(s);
        rotate_update_kernel<<<BN / 8, 256>>>(s, out, write_aux);
    }
    if (write_aux) finalize_loss_kernel<<<1, 32>>>(out);
}

// round 17
// speedup vs baseline: 1.6370x; 1.6370x over previous
#include <cuda_runtime.h>
#include <cuda_bf16.h>
#include <math.h>
#include <stdint.h>

// Problem constants
#define BN     16384           // B*N tokens
#define DIM    512
#define NC     4096            // codes per stage
#define NQ     4               // stages
#define CBSZ   (NC * DIM)      // floats per stage codebook
#define QOUT_ELEMS  (BN * DIM)               // 8388608
#define IDX_OFF     QOUT_ELEMS
#define IDX_ELEMS   (BN * NQ)                // 65536
#define LOSS_OFF    (IDX_OFF + IDX_ELEMS)
#define OUT_FULL    (LOSS_OFF + NQ)

typedef unsigned long long ull;

// ---------------- device scratch (static globals; no runtime alloc) ----------
__device__ float  g_cbn[(size_t)NQ * CBSZ];     // normalized implicit codebooks (32MB)
__device__ float  g_res[(size_t)BN * DIM];      // residual (32MB)
__device__ float  g_innorm[BN];                 // 1/||residual|| per token
__device__ __align__(16) __nv_bfloat16 g_cbh[(size_t)NQ * CBSZ];  // cb_n hi (16MB)
__device__ __align__(16) __nv_bfloat16 g_xh[(size_t)BN * DIM];    // x_n hi (16MB)
__device__ ull    g_best[BN];                   // packed (keyed exact sim, ~idx)
__device__ double g_loss[NQ];

// ---------------- helpers ------------------------------------------------------
__device__ __forceinline__ uint32_t smem_to_u32(const void* p) {
    uint32_t a;
    asm("{ .reg .u64 t; cvta.to.shared.u64 t, %1; cvt.u32.u64 %0, t; }" : "=r"(a) : "l"(p));
    return a;
}
__device__ __forceinline__ float warp_sum(float v) {
    #pragma unroll
    for (int o = 16; o; o >>= 1) v += __shfl_xor_sync(0xffffffffu, v, o);
    return v;
}

// order-preserving float<->uint key
__device__ __forceinline__ uint32_t kf(float v) {
    unsigned u = __float_as_uint(v);
    return (u & 0x80000000u) ? ~u : (u | 0x80000000u);
}
__device__ __forceinline__ float unkf(uint32_t k) {
    return (k & 0x80000000u) ? __uint_as_float(k ^ 0x80000000u)
                             : __uint_as_float(~k);
}
// packed (key, ~idx): atomicMax picks max value, then smallest index.
__device__ __forceinline__ ull pack_key(float v, int idx) {
    return ((ull)kf(v) << 32) | (ull)(0xFFFFFFFFu - (unsigned)idx);
}

// ldmatrix / mma (baseline PTX ISA — valid for plain sm_103 target)
__device__ __forceinline__ void ldm_x4(uint32_t* r, uint32_t addr) {
    asm volatile("ldmatrix.sync.aligned.m8n8.x4.shared.b16 {%0,%1,%2,%3}, [%4];"
        : "=r"(r[0]), "=r"(r[1]), "=r"(r[2]), "=r"(r[3]) : "r"(addr));
}
__device__ __forceinline__ void mma_bf16(float* d, const uint32_t* a, const uint32_t* b) {
    asm volatile(
        "mma.sync.aligned.m16n8k16.row.col.f32.bf16.bf16.f32 "
        "{%0,%1,%2,%3}, {%4,%5,%6,%7}, {%8,%9}, {%0,%1,%2,%3};"
        : "+f"(d[0]), "+f"(d[1]), "+f"(d[2]), "+f"(d[3])
        : "r"(a[0]), "r"(a[1]), "r"(a[2]), "r"(a[3]), "r"(b[0]), "r"(b[1]));
}
__device__ __forceinline__ void cp16(uint32_t saddr, const void* gptr) {
    asm volatile("cp.async.cg.shared.global [%0], [%1], 16;"
        :: "r"(saddr), "l"(gptr) : "memory");
}
#define CP_COMMIT() asm volatile("cp.async.commit_group;" ::: "memory")
#define CP_WAIT0()  asm volatile("cp.async.wait_group 0;" ::: "memory")

#define SWZ(off) ((off) ^ (((off) >> 3) & 0x70u))

// bf16 split packing: hi = bf16(x), lo = bf16(x - hi)
__device__ __forceinline__ uint32_t pack_bf16(float e0, float e1) {
    uint32_t r; asm("cvt.rn.bf16x2.f32 %0, %1, %2;" : "=r"(r) : "f"(e1), "f"(e0)); return r;
}
__device__ __forceinline__ float bflo(uint32_t p) { return __uint_as_float(p << 16); }
__device__ __forceinline__ float bfhi(uint32_t p) { return __uint_as_float(p & 0xffff0000u); }

__device__ __forceinline__ void cvt_store8(char* hb, char* lb, uint32_t sw,
                                           float4 a, float4 b) {
    uint4 hv, lv;
    hv.x = pack_bf16(a.x, a.y); hv.y = pack_bf16(a.z, a.w);
    hv.z = pack_bf16(b.x, b.y); hv.w = pack_bf16(b.z, b.w);
    lv.x = pack_bf16(a.x - bflo(hv.x), a.y - bfhi(hv.x));
    lv.y = pack_bf16(a.z - bflo(hv.y), a.w - bfhi(hv.y));
    lv.z = pack_bf16(b.x - bflo(hv.z), b.y - bfhi(hv.z));
    lv.w = pack_bf16(b.z - bflo(hv.w), b.w - bfhi(hv.w));
    *(uint4*)(hb + sw) = hv;
    *(uint4*)(lb + sw) = lv;
}

// hi-only split of 4 dims
__device__ __forceinline__ uint2 split4h(float4 v) {
    uint2 h;
    h.x = pack_bf16(v.x, v.y); h.y = pack_bf16(v.z, v.w);
    return h;
}

// ---------------- misc small kernels -----------------------------------------
__global__ void finalize_loss_kernel(float* out) {
    if (threadIdx.x < NQ)
        out[LOSS_OFF + threadIdx.x] =
            (float)(g_loss[threadIdx.x] * 1.25 / (double)QOUT_ELEMS);
}

// residual = x ; inv = 1/max(||x||,1e-12) ; bf16 hi of x*inv ; zero g_best/loss
__global__ void init_xr_kernel(const float* __restrict__ x) {
    int row = blockIdx.x;
    int t   = threadIdx.x;
    const float4* xr = (const float4*)(x + (size_t)row * DIM);
    float4 v = xr[t];
    float s = v.x * v.x + v.y * v.y + v.z * v.z + v.w * v.w;
    s = warp_sum(s);
    __shared__ float ps[4];
    if ((t & 31) == 0) ps[t >> 5] = s;
    __syncthreads();
    float tot = ps[0] + ps[1] + ps[2] + ps[3];
    float inv = 1.0f / fmaxf(sqrtf(tot), 1e-12f);
    ((float4*)(g_res + (size_t)row * DIM))[t] = v;
    if (t == 0) {
        g_innorm[row] = inv;
        g_best[row] = 0ull;                        // replaces zero_state kernel
        if (row == 0) {
            #pragma unroll
            for (int q = 0; q < NQ; q++) g_loss[q] = 0.0;
        }
    }
    float4 n = make_float4(v.x * inv, v.y * inv, v.z * inv, v.w * inv);
    ((uint2*)(g_xh + (size_t)row * DIM))[t] = split4h(n);
}

// in-place row l2norm of g_cbn + bf16 hi split (one block per row)
__global__ void cb_norm_kernel() {
    size_t row = blockIdx.x;
    int t = threadIdx.x;
    float4* r = (float4*)(g_cbn + row * DIM);
    float4 v = r[t];
    float s = v.x * v.x + v.y * v.y + v.z * v.z + v.w * v.w;
    s = warp_sum(s);
    __shared__ float ps[4];
    if ((t & 31) == 0) ps[t >> 5] = s;
    __syncthreads();
    float tot = ps[0] + ps[1] + ps[2] + ps[3];
    float inv = 1.0f / fmaxf(sqrtf(tot), 1e-12f);
    float4 n = make_float4(v.x * inv, v.y * inv, v.z * inv, v.w * inv);
    r[t] = n;
    ((uint2*)(g_cbh + row * DIM))[t] = split4h(n);
}

// ============ implicit codebook GEMM via bf16 split-2 mma ======================
#define XH_O 0
#define XL_O 16384
#define CH_O 32768
#define CL_O 49152
#define CB_SMEM 131072            // 2 x 64KB buffers

__global__ void __launch_bounds__(256, 1)
cb_gemm_mma_kernel(const float* __restrict__ codebooks, const float* __restrict__ weights) {
    extern __shared__ __align__(16) char smem[];
    uint32_t sb = smem_to_u32(smem);

    int tid  = threadIdx.x;
    int lane = tid & 31;
    int warp = tid >> 5;
    int wm = warp & 3;
    int wn = warp >> 2;

    int stage = blockIdx.z;
    int m0 = blockIdx.x * 128;    // codes
    int n0 = blockIdx.y * 128;    // dims
    const float* A  = codebooks + (size_t)stage * NC * DIM;
    const float* Bw = weights   + (size_t)stage * DIM * DIM;

    int srow[4], sslot[4];
    uint32_t ssw[4];
    #pragma unroll
    for (int it = 0; it < 4; it++) {
        int item = it * 256 + tid;
        srow[it]  = item >> 3;
        sslot[it] = item & 7;
        uint32_t off = (uint32_t)srow[it] * 128u + (uint32_t)sslot[it] * 16u;
        ssw[it] = SWZ(off);
    }

    int a_r = wm * 32 + (lane & 15);
    int a_c = (lane >> 4) << 4;
    int b_r = wn * 64 + ((lane >> 4) << 3) + (lane & 7);
    int b_c = ((lane >> 3) & 1) << 4;

    float acc[2][8][4];
    #pragma unroll
    for (int mf = 0; mf < 2; mf++)
        #pragma unroll
        for (int nf = 0; nf < 8; nf++)
            #pragma unroll
            for (int q = 0; q < 4; q++) acc[mf][nf][q] = 0.f;

    float4 xv[4][2], cv[4][2];
    #pragma unroll
    for (int it = 0; it < 4; it++) {
        const float* xp = A  + (size_t)(m0 + srow[it]) * DIM + sslot[it] * 8;
        const float* cp = Bw + (size_t)(n0 + srow[it]) * DIM + sslot[it] * 8;
        xv[it][0] = *(const float4*)xp;  xv[it][1] = *(const float4*)(xp + 4);
        cv[it][0] = *(const float4*)cp;  cv[it][1] = *(const float4*)(cp + 4);
    }
    #pragma unroll
    for (int it = 0; it < 4; it++) {
        cvt_store8(smem + XH_O, smem + XL_O, ssw[it], xv[it][0], xv[it][1]);
        cvt_store8(smem + CH_O, smem + CL_O, ssw[it], cv[it][0], cv[it][1]);
    }
    __syncthreads();

    for (int g = 0; g < 8; g++) {
        if (g + 1 < 8) {
            int k1 = (g + 1) * 64;
            #pragma unroll
            for (int it = 0; it < 4; it++) {
                const float* xp = A  + (size_t)(m0 + srow[it]) * DIM + k1 + sslot[it] * 8;
                const float* cp = Bw + (size_t)(n0 + srow[it]) * DIM + k1 + sslot[it] * 8;
                xv[it][0] = *(const float4*)xp;  xv[it][1] = *(const float4*)(xp + 4);
                cv[it][0] = *(const float4*)cp;  cv[it][1] = *(const float4*)(cp + 4);
            }
        }
        uint32_t bufb = sb + (uint32_t)((g & 1) * 65536);
        #pragma unroll
        for (int ks = 0; ks < 4; ks++) {
            uint32_t ah[2][4], al[2][4];
            #pragma unroll
            for (int mf = 0; mf < 2; mf++) {
                uint32_t off = (uint32_t)(a_r + mf * 16) * 128u + (uint32_t)(ks * 32 + a_c);
                uint32_t sw = SWZ(off);
                ldm_x4(ah[mf], bufb + XH_O + sw);
                ldm_x4(al[mf], bufb + XL_O + sw);
            }
            uint32_t bh[16], bl[16];
            #pragma unroll
            for (int nf2 = 0; nf2 < 4; nf2++) {
                uint32_t off = (uint32_t)(b_r + nf2 * 16) * 128u + (uint32_t)(ks * 32 + b_c);
                uint32_t sw = SWZ(off);
                ldm_x4(&bh[nf2 * 4], bufb + CH_O + sw);
                ldm_x4(&bl[nf2 * 4], bufb + CL_O + sw);
            }
            #pragma unroll
            for (int mf = 0; mf < 2; mf++)
                #pragma unroll
                for (int nf = 0; nf < 8; nf++) {
                    mma_bf16(acc[mf][nf], ah[mf], &bh[nf * 2]);
                    mma_bf16(acc[mf][nf], ah[mf], &bl[nf * 2]);
                    mma_bf16(acc[mf][nf], al[mf], &bh[nf * 2]);
                }
        }
        if (g + 1 < 8) {
            char* nb = smem + ((g + 1) & 1) * 65536;
            #pragma unroll
            for (int it = 0; it < 4; it++) {
                cvt_store8(nb + XH_O, nb + XL_O, ssw[it], xv[it][0], xv[it][1]);
                cvt_store8(nb + CH_O, nb + CL_O, ssw[it], cv[it][0], cv[it][1]);
            }
        }
        __syncthreads();
    }

    float* out = g_cbn + (size_t)stage * CBSZ;
    int r0 = lane >> 2, c0 = (lane & 3) * 2;
    #pragma unroll
    for (int mf = 0; mf < 2; mf++) {
        int row = m0 + wm * 32 + mf * 16 + r0;
        #pragma unroll
        for (int nf = 0; nf < 8; nf++) {
            int col = n0 + wn * 64 + nf * 8 + c0;
            out[(size_t)row * DIM + col]           = acc[mf][nf][0];
            out[(size_t)row * DIM + col + 1]       = acc[mf][nf][1];
            out[(size_t)(row + 8) * DIM + col]     = acc[mf][nf][2];
            out[(size_t)(row + 8) * DIM + col + 1] = acc[mf][nf][3];
        }
    }
}

// ============ fused sim: running-best coarse + candidate lists + rescore =======
// CTA = (token-tile of 128) x (code-sixteenth of 256) -> 2048 CTAs, occ 2.
// Warp tile 2Mx4N. Tile boundary: phase A atomicMax per-row coarse best;
// phase B append codes within margin to per-row list. End: exact fp32 dots
// for surviving candidates, packed-atomicMax merge. 83KB smem.
#define FXH_O   0
#define FCH_O   16384
#define FBUFSZ  32768
#define BEST_O  65536                       // 128 x u32
#define CNT_O   (BEST_O + 512)              // 128 x int
#define OVF_O   (CNT_O + 512)               // 128 x int
#define CAND_O  (OVF_O + 512)               // 128 x 16 x u64
#define CAND_CAP 16
#define FUSED_SMEM (CAND_O + 128 * CAND_CAP * 8)   // 83456 B
#define FGTOT 16                            // 2 n-tiles x 8 k-chunks
#define RESCORE_MARGIN 0.009f

__global__ void __launch_bounds__(256, 2)
sim_fused_kernel(int stage) {
    extern __shared__ __align__(16) char smem[];
    uint32_t sb = smem_to_u32(smem);

    int tid  = threadIdx.x;
    int lane = tid & 31;
    int warp = tid >> 5;
    int wm = warp & 1;            // m offset wm*64
    int wn = warp >> 1;           // n offset wn*32

    int tilei = blockIdx.x >> 4;
    int six   = blockIdx.x & 15;
    int m0 = tilei * 128;
    int eb = six * 256;

    const char* xhp = (const char*)(g_xh + (size_t)m0 * DIM);
    const char* chp = (const char*)(g_cbh + (size_t)stage * CBSZ + (size_t)eb * DIM);

    uint32_t* best = (uint32_t*)(smem + BEST_O);
    int*      cnt  = (int*)(smem + CNT_O);
    int*      ovf  = (int*)(smem + OVF_O);
    ull*      cand = (ull*)(smem + CAND_O);

    if (tid < 128) { best[tid] = 0u; cnt[tid] = 0; ovf[tid] = 0; }

    int srow[4], sslot[4];
    uint32_t ssw[4];
    size_t roff[4];
    #pragma unroll
    for (int it = 0; it < 4; it++) {
        int item = it * 256 + tid;
        srow[it]  = item >> 3;
        sslot[it] = item & 7;
        uint32_t off = (uint32_t)srow[it] * 128u + (uint32_t)sslot[it] * 16u;
        ssw[it] = SWZ(off);
        roff[it] = (size_t)srow[it] * (DIM * 2) + (size_t)sslot[it] * 16;
    }

    int a_r = wm * 64 + (lane & 15);
    int a_c = (lane >> 4) << 4;
    int b_r = wn * 32 + ((lane >> 4) << 3) + (lane & 7);
    int b_c = ((lane >> 3) & 1) << 4;

    float acc[4][4][4];
    #pragma unroll
    for (int mf = 0; mf < 4; mf++)
        #pragma unroll
        for (int nf = 0; nf < 4; nf++)
            #pragma unroll
            for (int q = 0; q < 4; q++) acc[mf][nf][q] = 0.f;

    // prologue: async-copy chunk 0 into buf 0
    {
        uint32_t nb = sb;
        #pragma unroll
        for (int it = 0; it < 4; it++) {
            cp16(nb + FXH_O + ssw[it], xhp + roff[it]);
            cp16(nb + FCH_O + ssw[it], chp + roff[it]);
        }
        CP_COMMIT();
        CP_WAIT0();
        __syncthreads();
    }

    for (int gg = 0; gg < FGTOT; gg++) {
        if (gg + 1 < FGTOT) {
            int nt1 = (gg + 1) >> 3;
            size_t kb1 = (size_t)(((gg + 1) & 7) * 64) * 2;
            size_t cb1 = (size_t)(nt1 * 128) * (DIM * 2) + kb1;
            uint32_t nb = sb + (uint32_t)(((gg + 1) & 1) * FBUFSZ);
            #pragma unroll
            for (int it = 0; it < 4; it++) {
                cp16(nb + FXH_O + ssw[it], xhp + kb1 + roff[it]);
                cp16(nb + FCH_O + ssw[it], chp + cb1 + roff[it]);
            }
            CP_COMMIT();
        }
        uint32_t bufb = sb + (uint32_t)((gg & 1) * FBUFSZ);
        #pragma unroll
        for (int ks = 0; ks < 4; ks++) {
            uint32_t ah[4][4];
            #pragma unroll
            for (int mf = 0; mf < 4; mf++) {
                uint32_t off = (uint32_t)(a_r + mf * 16) * 128u + (uint32_t)(ks * 32 + a_c);
                ldm_x4(ah[mf], bufb + FXH_O + SWZ(off));
            }
            uint32_t bh[8];
            #pragma unroll
            for (int nf2 = 0; nf2 < 2; nf2++) {
                uint32_t off = (uint32_t)(b_r + nf2 * 16) * 128u + (uint32_t)(ks * 32 + b_c);
                ldm_x4(&bh[nf2 * 4], bufb + FCH_O + SWZ(off));
            }
            #pragma unroll
            for (int mf = 0; mf < 4; mf++)
                #pragma unroll
                for (int nf = 0; nf < 4; nf++)
                    mma_bf16(acc[mf][nf], ah[mf], &bh[nf * 2]);
        }
        // tile boundary: update per-row best, then append in-margin candidates
        if ((gg & 7) == 7) {
            int nt = gg >> 3;
            // phase A: per-row max of this thread's values -> atomicMax
            #pragma unroll
            for (int mf = 0; mf < 4; mf++) {
                int r0 = wm * 64 + mf * 16 + (lane >> 2);
                float v0 = -1e30f, v1 = -1e30f;
                #pragma unroll
                for (int nf = 0; nf < 4; nf++) {
                    v0 = fmaxf(v0, fmaxf(acc[mf][nf][0], acc[mf][nf][1]));
                    v1 = fmaxf(v1, fmaxf(acc[mf][nf][2], acc[mf][nf][3]));
                }
                atomicMax(&best[r0], kf(v0));
                atomicMax(&best[r0 + 8], kf(v1));
            }
            __syncthreads();
            // phase B: append candidates within margin of (current) best
            #pragma unroll
            for (int mf = 0; mf < 4; mf++) {
                int r0 = wm * 64 + mf * 16 + (lane >> 2);
                int r1 = r0 + 8;
                float t0 = unkf(best[r0]) - RESCORE_MARGIN;
                float t1 = unkf(best[r1]) - RESCORE_MARGIN;
                #pragma unroll
                for (int nf = 0; nf < 4; nf++) {
                    int code = eb + nt * 128 + wn * 32 + (lane & 3) * 2 + nf * 8;
                    float v0 = acc[mf][nf][0], v1 = acc[mf][nf][1];
                    float v2 = acc[mf][nf][2], v3 = acc[mf][nf][3];
                    if (v0 >= t0) {
                        int p = atomicAdd(&cnt[r0], 1);
                        if (p < CAND_CAP) cand[r0 * CAND_CAP + p] = ((ull)kf(v0) << 32) | (unsigned)code;
                        else ovf[r0] = 1;
                    }
                    if (v1 >= t0) {
                        int p = atomicAdd(&cnt[r0], 1);
                        if (p < CAND_CAP) cand[r0 * CAND_CAP + p] = ((ull)kf(v1) << 32) | (unsigned)(code + 1);
                        else ovf[r0] = 1;
                    }
                    if (v2 >= t1) {
                        int p = atomicAdd(&cnt[r1], 1);
                        if (p < CAND_CAP) cand[r1 * CAND_CAP + p] = ((ull)kf(v2) << 32) | (unsigned)code;
                        else ovf[r1] = 1;
                    }
                    if (v3 >= t1) {
                        int p = atomicAdd(&cnt[r1], 1);
                        if (p < CAND_CAP) cand[r1 * CAND_CAP + p] = ((ull)kf(v3) << 32) | (unsigned)(code + 1);
                        else ovf[r1] = 1;
                    }
                    acc[mf][nf][0] = 0.f; acc[mf][nf][1] = 0.f;
                    acc[mf][nf][2] = 0.f; acc[mf][nf][3] = 0.f;
                }
            }
        }
        if (gg + 1 < FGTOT) CP_WAIT0();
        __syncthreads();
    }

    // ---------- rescore: each warp owns 16 tokens ----------
    const float* cbs = g_cbn + (size_t)stage * CBSZ;
    for (int ti = 0; ti < 16; ti++) {
        int row = warp * 16 + ti;
        int token = m0 + row;

        float invx = g_innorm[token];
        const float4* xr = (const float4*)(g_res + (size_t)token * DIM);
        float4 xv[4];
        #pragma unroll
        for (int k = 0; k < 4; k++) {
            float4 v = xr[lane + k * 32];
            xv[k] = make_float4(v.x * invx, v.y * invx, v.z * invx, v.w * invx);
        }

        float thr = unkf(best[row]) - RESCORE_MARGIN;
        float bestv = -1e30f;
        int   besti = NC;

        if (!ovf[row]) {
            int n = cnt[row]; if (n > CAND_CAP) n = CAND_CAP;
            for (int i = 0; i < n; i++) {
                ull e = cand[row * CAND_CAP + i];
                float cv = unkf((uint32_t)(e >> 32));
                if (cv < thr) continue;     // stale-best over-append: skip
                int code = (int)(e & 0xFFFFFFFFull);
                const float4* cbr = (const float4*)(cbs + (size_t)code * DIM);
                float s = 0.f;
                #pragma unroll
                for (int k = 0; k < 4; k++) {
                    float4 c = cbr[lane + k * 32];
                    s += c.x * xv[k].x + c.y * xv[k].y + c.z * xv[k].z + c.w * xv[k].w;
                }
                s = warp_sum(s);
                if (s > bestv || (s == bestv && code < besti)) { bestv = s; besti = code; }
            }
        } else {
            // overflow fallback: exact dots over the whole sixteenth
            for (int c = 0; c < 256; c++) {
                int code = eb + c;
                const float4* cbr = (const float4*)(cbs + (size_t)code * DIM);
                float s = 0.f;
                #pragma unroll
                for (int k = 0; k < 4; k++) {
                    float4 cc = cbr[lane + k * 32];
                    s += cc.x * xv[k].x + cc.y * xv[k].y + cc.z * xv[k].z + cc.w * xv[k].w;
                }
                s = warp_sum(s);
                if (s > bestv || (s == bestv && code < besti)) { bestv = s; besti = code; }
            }
        }
        if (lane == 0)
            atomicMax(&g_best[token], pack_key(bestv, besti));
    }
}

// ---------------- rotation-trick update per token ------------------------------
// Also resets g_best[token] = 0 for the next stage.
__global__ void rotate_update_kernel(int stage, float* __restrict__ out, int write_aux) {
    int warp = threadIdx.x >> 5;
    int lane = threadIdx.x & 31;
    int token = blockIdx.x * 8 + warp;

    float4* rr = (float4*)(g_res + (size_t)token * DIM);
    float invx = g_innorm[token];
    ull bkey = g_best[token];
    int code = (int)(0xFFFFFFFFu - (unsigned)(bkey & 0xFFFFFFFFull));
    const float4* qr = (const float4*)(g_cbn + (size_t)stage * CBSZ + (size_t)code * DIM);

    float4 xv[4], qv[4], rv[4];
    float see = 0.f, stt = 0.f, set = 0.f;
    #pragma unroll
    for (int j = 0; j < 4; j++) {
        rv[j] = rr[lane + j * 32];
        xv[j] = make_float4(rv[j].x * invx, rv[j].y * invx,
                            rv[j].z * invx, rv[j].w * invx);
        qv[j] = qr[lane + j * 32];
        see += xv[j].x * xv[j].x + xv[j].y * xv[j].y + xv[j].z * xv[j].z + xv[j].w * xv[j].w;
        stt += qv[j].x * qv[j].x + qv[j].y * qv[j].y + qv[j].z * qv[j].z + qv[j].w * qv[j].w;
        set += xv[j].x * qv[j].x + xv[j].y * qv[j].y + xv[j].z * qv[j].z + xv[j].w * qv[j].w;
    }
    see = warp_sum(see); stt = warp_sum(stt); set = warp_sum(set);

    float ns = sqrtf(see), nt = sqrtf(stt);
    float eu = see / ns;
    float eq = set / nt;
    float nw2 = 2.f + 2.f * set / (ns * nt);
    float nw = fmaxf(sqrtf(nw2), 1e-12f);
    float cw = 2.f * (eu + eq) / (nw * nw);
    float ax = (nt / ns) * (1.f - cw / ns);
    float aq = (2.f * eu - cw) / ns;
    float scc = see - 2.f * set + stt;

    float4* qo = (float4*)(out + (size_t)token * DIM);
    float rn2 = 0.f;
    float4 rnv[4];
    #pragma unroll
    for (int j = 0; j < 4; j++) {
        float4 o;
        o.x = ax * xv[j].x + aq * qv[j].x;
        o.y = ax * xv[j].y + aq * qv[j].y;
        o.z = ax * xv[j].z + aq * qv[j].z;
        o.w = ax * xv[j].w + aq * qv[j].w;
        if (stage == 0) {
            qo[lane + j * 32] = o;
        } else {
            float4 prev = qo[lane + j * 32];
            prev.x += o.x; prev.y += o.y; prev.z += o.z; prev.w += o.w;
            qo[lane + j * 32] = prev;
        }
        float4 rn;
        rn.x = rv[j].x - o.x; rn.y = rv[j].y - o.y;
        rn.z = rv[j].z - o.z; rn.w = rv[j].w - o.w;
        rr[lane + j * 32] = rn;
        rnv[j] = rn;
        rn2 += rn.x * rn.x + rn.y * rn.y + rn.z * rn.z + rn.w * rn.w;
    }
    if (stage < NQ - 1) {
        rn2 = warp_sum(rn2);
        float inv = 1.f / fmaxf(sqrtf(rn2), 1e-12f);
        if (lane == 0) g_innorm[token] = inv;
        uint2* xhw = (uint2*)(g_xh + (size_t)token * DIM);
        #pragma unroll
        for (int j = 0; j < 4; j++) {
            float4 n = make_float4(rnv[j].x * inv, rnv[j].y * inv,
                                   rnv[j].z * inv, rnv[j].w * inv);
            xhw[lane + j * 32] = split4h(n);
        }
    }
    if (lane == 0) {
        if (write_aux)
            out[IDX_OFF + (size_t)token * NQ + stage] = (float)code;
        g_best[token] = 0ull;    // reset for next stage
    }

    __shared__ float wscc[8];
    if (lane == 0) wscc[warp] = scc;
    __syncthreads();
    if (threadIdx.x == 0) {
        float s = 0.f;
        #pragma unroll
        for (int w = 0; w < 8; w++) s += wscc[w];
        atomicAdd(&g_loss[stage], (double)s);
    }
}

// ---------------- launch ------------------------------------------------------
extern "C" void kernel_launch(void* const* d_in, const int* in_sizes, int n_in,
                              void* d_out, int out_size) {
    const float* x         = (const float*)d_in[0];
    const float* codebooks = (const float*)d_in[1];
    const float* weights   = (const float*)d_in[2];
    float* out = (float*)d_out;
    int write_aux = (out_size >= OUT_FULL) ? 1 : 0;

    cudaFuncSetAttribute(cb_gemm_mma_kernel,
                         cudaFuncAttributeMaxDynamicSharedMemorySize, CB_SMEM);
    cudaFuncSetAttribute(sim_fused_kernel,
                         cudaFuncAttributeMaxDynamicSharedMemorySize, FUSED_SMEM);

    cb_gemm_mma_kernel<<<dim3(NC / 128, DIM / 128, NQ), 256, CB_SMEM>>>(codebooks, weights);
    cb_norm_kernel<<<NQ * NC, 128>>>();
    init_xr_kernel<<<BN, 128>>>(x);
    for (int s = 0; s < NQ; s++) {
        sim_fused_kernel<<<(BN / 128) * 16, 256, FUSED_SMEM>>>(s);
        rotate_update_kernel<<<BN / 8, 256>>>(s, out, write_aux);
    }
    if (write_aux) finalize_loss_kernel<<<1, 32>>>(out);
}